// round 8
// baseline (speedup 1.0000x reference)
#include <cuda_runtime.h>

// LSTM autoencoder: enc (F=32 -> H=64), dec (H=64 -> F=32), B=512, T=1024.
// 128 blocks x 768 threads (6 warps/SMSP), 4 batch rows/block.
// tid = ug*8 + s:  ug = unit (0..63 enc, 64..95 dec), s = k-EIGHTH lane.
// Thread holds all 4 gates (i,f,g,o) over k-eighth [12s, 12s+12):
//   4 x 6 packed f32x2 = 24 ull weight regs (48 regs) -- fits the 85-reg cap
//   (R5 spilled because its layout needed 96 weight regs at this cap).
// Row-permuted accumulators acc[l] = partial(row (s^l)&3), l in [0,4);
// reduction per gate: xor1, xor2 (within 4-lane subgroup) then xor4 to merge
// subgroups -> every lane holds complete gates for row s&3 (s and s^4 are
// duplicates; stores predicated on s < 4). 4 shfl per gate, 16 total.
// XHP = 104 (== 8 mod 32): bank base 8*((s^l)&3) + 12s is distinct mod 32
// for every l -> conflict-free LDS.128. (100 would conflict for THIS layout.)
// Biases in SMEM (register relief). Double-buffered xh state, ONE
// __syncthreads per step, decoder lags encoder by one step.

#define T_STEPS 1024
#define FDIM    32
#define HDIM    64
#define ROWS    4
#define NBLK    128
#define NTHR    768
#define XHP     104

#define OFF_XHE(b) ((b) * (ROWS * XHP))
#define OFF_XHD(b) (2 * ROWS * XHP + (b) * (ROWS * XHP))
#define OFF_BE     (4 * ROWS * XHP)           // enc bias [256]
#define OFF_BD     (OFF_BE + 256)             // dec bias [128]
#define SMEMN      (OFF_BD + 128)             // 2048 floats = 8 KB

typedef unsigned long long ull;
union U64F2 { ull u; float2 f; };

__device__ __forceinline__ ull pk(float lo, float hi) {
    U64F2 u; u.f = make_float2(lo, hi); return u.u;
}
__device__ __forceinline__ ull ffma2(ull a, ull b, ull c) {
    ull d;
    asm("fma.rn.f32x2 %0, %1, %2, %3;" : "=l"(d) : "l"(a), "l"(b), "l"(c));
    return d;
}
__device__ __forceinline__ float hsum2(ull a) {
    U64F2 u; u.u = a; return u.f.x + u.f.y;
}
__device__ __forceinline__ float sigf(float x) {
    return __fdividef(1.0f, 1.0f + __expf(-x));
}
__device__ __forceinline__ float tanh_fast(float x) {
    float e = __expf(2.0f * x);
    return 1.0f - __fdividef(2.0f, e + 1.0f);
}

__global__ void __launch_bounds__(NTHR, 1) lstm_ae_kernel(
    const float* __restrict__ x,
    const float* __restrict__ ew_ih, const float* __restrict__ ew_hh,
    const float* __restrict__ eb_ih, const float* __restrict__ eb_hh,
    const float* __restrict__ dw_ih, const float* __restrict__ dw_hh,
    const float* __restrict__ db_ih, const float* __restrict__ db_hh,
    float* __restrict__ out)
{
    __shared__ __align__(16) float sm[SMEMN];
    const int tid = threadIdx.x;
    const int b0  = blockIdx.x * ROWS;

    const int ug   = tid >> 3;            // unit 0..95 (warp = 4 units, uniform)
    const bool dec = (ug >= 64);
    const int u    = dec ? (ug - 64) : ug;
    const int s    = tid & 7;             // k-eighth lane
    const int kb   = 12 * s;
    const int rme  = s & 3;               // my elementwise row

    // ---- weights -> registers: 4 gates x 12 k-floats (6 packed each) ----
    ull wI[6], wF[6], wG[6], wO[6];
    {
        const int U  = dec ? FDIM : HDIM;
        const int KI = dec ? HDIM : FDIM;
        const int KH = dec ? FDIM : HDIM;
        const float* wih = dec ? dw_ih : ew_ih;
        const float* whh = dec ? dw_hh : ew_hh;
        #pragma unroll
        for (int j = 0; j < 6; ++j) {
            const int k0 = kb + 2 * j, k1 = k0 + 1;
            #define WLD(ARR, GOFF)                                              \
            {                                                                   \
                const int g = u + (GOFF) * U;                                   \
                float lo = (k0 < KI) ? wih[g * KI + k0] : whh[g * KH + (k0 - KI)]; \
                float hi = (k1 < KI) ? wih[g * KI + k1] : whh[g * KH + (k1 - KI)]; \
                ARR[j] = pk(lo, hi);                                            \
            }
            WLD(wI, 0) WLD(wF, 1) WLD(wG, 2) WLD(wO, 3)
            #undef WLD
        }
    }

    // ---- biases -> SMEM; init state; x(0) in; prefetch x(1) ----
    for (int i = tid; i < 4 * ROWS * XHP; i += NTHR) sm[i] = 0.0f;
    __syncthreads();
    if (tid < 256) sm[OFF_BE + tid] = eb_ih[tid] + eb_hh[tid];
    else if (tid < 384) sm[OFF_BD + tid - 256] = db_ih[tid - 256] + db_hh[tid - 256];
    float x_pref = 0.0f;
    if (dec && s < 4) {   // 32 units x 4 rows cover the 4x32 x-slots
        sm[OFF_XHE(0) + rme * XHP + u] =
            x[((size_t)(b0 + rme) * T_STEPS + 0) * FDIM + u];
        x_pref = x[((size_t)(b0 + rme) * T_STEPS + 1) * FDIM + u];
    }
    __syncthreads();

    // bias base for this unit (read via LDS each step; saves registers)
    const float* bias = sm + (dec ? OFF_BD : OFF_BE);
    const int U2 = dec ? FDIM : HDIM;

    // row offsets in permuted order (s^l)&3
    const int ro0 = ((s)     & 3) * XHP;
    const int ro1 = ((s ^ 1) & 3) * XHP;
    const int ro2 = ((s ^ 2) & 3) * XHP;
    const int ro3 = ((s ^ 3) & 3) * XHP;

    float c_st = 0.0f;

    for (int it = 0; it <= T_STEPS; ++it) {
        const int rb = it & 1, wb = rb ^ 1;
        const bool live = dec ? (it > 0) : (it < T_STEPS);
        const float* xh = sm + (dec ? OFF_XHD(rb) : OFF_XHE(rb)) + kb;

        // ===== FMA: 4 gates x 4 rows (row-permuted accumulators) =====
        float aI[4], aF[4], aG[4], aO[4];
        {
            #define DO_ROW(L, RO)                                            \
            {                                                                \
                const ulonglong2* hp =                                       \
                    reinterpret_cast<const ulonglong2*>(xh + (RO));          \
                ulonglong2 v0 = hp[0];                                       \
                ulonglong2 v1 = hp[1];                                       \
                ulonglong2 v2 = hp[2];                                       \
                ull cI, cF, cG, cO;                                          \
                cI = ffma2(wI[0], v0.x, 0ull);                               \
                cF = ffma2(wF[0], v0.x, 0ull);                               \
                cG = ffma2(wG[0], v0.x, 0ull);                               \
                cO = ffma2(wO[0], v0.x, 0ull);                               \
                cI = ffma2(wI[1], v0.y, cI);                                 \
                cF = ffma2(wF[1], v0.y, cF);                                 \
                cG = ffma2(wG[1], v0.y, cG);                                 \
                cO = ffma2(wO[1], v0.y, cO);                                 \
                cI = ffma2(wI[2], v1.x, cI);                                 \
                cF = ffma2(wF[2], v1.x, cF);                                 \
                cG = ffma2(wG[2], v1.x, cG);                                 \
                cO = ffma2(wO[2], v1.x, cO);                                 \
                cI = ffma2(wI[3], v1.y, cI);                                 \
                cF = ffma2(wF[3], v1.y, cF);                                 \
                cG = ffma2(wG[3], v1.y, cG);                                 \
                cO = ffma2(wO[3], v1.y, cO);                                 \
                cI = ffma2(wI[4], v2.x, cI);                                 \
                cF = ffma2(wF[4], v2.x, cF);                                 \
                cG = ffma2(wG[4], v2.x, cG);                                 \
                cO = ffma2(wO[4], v2.x, cO);                                 \
                cI = ffma2(wI[5], v2.y, cI);                                 \
                cF = ffma2(wF[5], v2.y, cF);                                 \
                cG = ffma2(wG[5], v2.y, cG);                                 \
                cO = ffma2(wO[5], v2.y, cO);                                 \
                aI[L] = hsum2(cI); aF[L] = hsum2(cF);                        \
                aG[L] = hsum2(cG); aO[L] = hsum2(cO);                        \
            }
            DO_ROW(0, ro0)
            DO_ROW(1, ro1)
            DO_ROW(2, ro2)
            DO_ROW(3, ro3)
            #undef DO_ROW
        }

        // ===== reduction: xor1 + xor2 over 4-lane subgroup, xor4 merge =====
        #define REDUCE(A, OUTV)                                              \
        {                                                                    \
            float t0 = A[0] + __shfl_xor_sync(0xFFFFFFFFu, A[1], 1);         \
            float t1 = A[2] + __shfl_xor_sync(0xFFFFFFFFu, A[3], 1);         \
            float f  = t0 + __shfl_xor_sync(0xFFFFFFFFu, t1, 2);             \
            OUTV = f + __shfl_xor_sync(0xFFFFFFFFu, f, 4);                   \
        }
        float gi, gf, gg, go;
        REDUCE(aI, gi) REDUCE(aF, gf) REDUCE(aG, gg) REDUCE(aO, go)
        #undef REDUCE
        gi += bias[u];
        gf += bias[u + U2];
        gg += bias[u + 2 * U2];
        go += bias[u + 3 * U2];

        // ===== elementwise: all lanes compute (s and s^4 duplicate),
        //       stores predicated on s < 4 =====
        if (live) {
            float iv = sigf(gi), fv = sigf(gf);
            float gv = tanh_fast(gg), ov = sigf(go);
            c_st = fv * c_st + iv * gv;
            float hv = ov * tanh_fast(c_st);
            if (s < 4) {
                if (!dec) {
                    sm[OFF_XHE(wb) + rme * XHP + FDIM + u] = hv;  // enc recur
                    sm[OFF_XHD(wb) + rme * XHP + u]        = hv;  // dec input
                } else {
                    sm[OFF_XHD(wb) + rme * XHP + HDIM + u] = hv;  // dec recur
                    out[((size_t)(b0 + rme) * T_STEPS + (it - 1)) * FDIM + u] = hv;
                }
            }
        }
        if (dec && s < 4) {   // x pipeline
            if (it + 1 < T_STEPS)
                sm[OFF_XHE(wb) + rme * XHP + u] = x_pref;
            if (it + 2 < T_STEPS)
                x_pref = x[((size_t)(b0 + rme) * T_STEPS + (it + 2)) * FDIM + u];
        }
        __syncthreads();
    }
}

extern "C" void kernel_launch(void* const* d_in, const int* in_sizes, int n_in,
                              void* d_out, int out_size)
{
    (void)in_sizes; (void)n_in; (void)out_size;
    lstm_ae_kernel<<<NBLK, NTHR>>>(
        (const float*)d_in[0],
        (const float*)d_in[1], (const float*)d_in[2],
        (const float*)d_in[3], (const float*)d_in[4],
        (const float*)d_in[5], (const float*)d_in[6],
        (const float*)d_in[7], (const float*)d_in[8],
        (float*)d_out);
}

// round 9
// speedup vs baseline: 1.5182x; 1.5182x over previous
#include <cuda_runtime.h>

// LSTM autoencoder: enc (F=32 -> H=64), dec (H=64 -> F=32), B=512, T=1024.
// 128 blocks x 384 threads, 4 batch rows/block. WARP-SPECIALIZED:
//   warps 0-7  (256 thr) = encoder group, own loop
//   warps 8-11 (128 thr) = decoder group, own loop
// Dependency is one-directional (enc never reads dec), so groups sync only via
// named-barrier producer/consumer pairs (bar.arrive = release, bar.sync = acq):
//   h_enc ring XHD[3]: enc writes slot it%3 then arrives HBAR_s; dec syncs
//   HBAR_s, reads, arrives CBAR_s; enc syncs CBAR_s at loop top (credit, and
//   doubles as the enc-internal barrier). One sync + one arrive per step per
//   group, NO __syncthreads in the loop, up to ~3 steps of enc/dec skew so
//   dec FMA overlaps enc tail (shfl/MUFU/stores) and vice versa.
// Compute core = R7: tid = ug*4+q, thread owns all 4 gates of its unit over
// k-quarter [24q,24q+24) (48 packed weight regs), row-permuted accumulators,
// 3-shfl butterfly per gate, XHP=100 -> conflict-free LDS.128.

#define T_STEPS 1024
#define FDIM    32
#define HDIM    64
#define ROWS    4
#define NBLK    128
#define NTHR    384
#define XHP     100

// SMEM floats: XHE[2][4][XHP], XHD[3][4][XHP]
#define OFF_XHE(b) ((b) * (ROWS * XHP))
#define OFF_XHD(s) (2 * ROWS * XHP + (s) * (ROWS * XHP))
#define SMEMN      (5 * ROWS * XHP)

// named barrier ids (0 reserved for syncthreads): CBAR_s = 1+s, HBAR_s = 4+s
#define BAR_SYNC(id, n)   asm volatile("bar.sync %0, %1;"   :: "r"(id), "r"(n) : "memory")
#define BAR_ARRIVE(id, n) asm volatile("bar.arrive %0, %1;" :: "r"(id), "r"(n) : "memory")

typedef unsigned long long ull;
union U64F2 { ull u; float2 f; };

__device__ __forceinline__ ull pk(float lo, float hi) {
    U64F2 u; u.f = make_float2(lo, hi); return u.u;
}
__device__ __forceinline__ ull ffma2(ull a, ull b, ull c) {
    ull d;
    asm("fma.rn.f32x2 %0, %1, %2, %3;" : "=l"(d) : "l"(a), "l"(b), "l"(c));
    return d;
}
__device__ __forceinline__ float hsum2(ull a) {
    U64F2 u; u.u = a; return u.f.x + u.f.y;
}
__device__ __forceinline__ float sigf(float x) {
    return __fdividef(1.0f, 1.0f + __expf(-x));
}
__device__ __forceinline__ float tanh_fast(float x) {
    float e = __expf(2.0f * x);
    return 1.0f - __fdividef(2.0f, e + 1.0f);
}

__global__ void __launch_bounds__(NTHR, 1) lstm_ae_kernel(
    const float* __restrict__ x,
    const float* __restrict__ ew_ih, const float* __restrict__ ew_hh,
    const float* __restrict__ eb_ih, const float* __restrict__ eb_hh,
    const float* __restrict__ dw_ih, const float* __restrict__ dw_hh,
    const float* __restrict__ db_ih, const float* __restrict__ db_hh,
    float* __restrict__ out)
{
    __shared__ __align__(16) float sm[SMEMN];
    const int tid = threadIdx.x;
    const int b0  = blockIdx.x * ROWS;

    const int ug   = tid >> 2;            // unit 0..95; warps 0-7 enc, 8-11 dec
    const bool dec = (ug >= 64);
    const int u    = dec ? (ug - 64) : ug;
    const int q    = tid & 3;             // k-quarter AND elementwise row
    const int kb   = 24 * q;

    // ---- weights -> registers: 4 gates x 24 k-floats (12 packed each) ----
    ull wI[12], wF[12], wG[12], wO[12];
    {
        const int U  = dec ? FDIM : HDIM;
        const int KI = dec ? HDIM : FDIM;
        const int KH = dec ? FDIM : HDIM;
        const float* wih = dec ? dw_ih : ew_ih;
        const float* whh = dec ? dw_hh : ew_hh;
        #pragma unroll
        for (int j = 0; j < 12; ++j) {
            const int k0 = kb + 2 * j, k1 = k0 + 1;
            #define WLD(ARR, GOFF)                                              \
            {                                                                   \
                const int g = u + (GOFF) * U;                                   \
                float lo = (k0 < KI) ? wih[g * KI + k0] : whh[g * KH + (k0 - KI)]; \
                float hi = (k1 < KI) ? wih[g * KI + k1] : whh[g * KH + (k1 - KI)]; \
                ARR[j] = pk(lo, hi);                                            \
            }
            WLD(wI, 0) WLD(wF, 1) WLD(wG, 2) WLD(wO, 3)
            #undef WLD
        }
    }

    // ---- biases for this unit ----
    const int U2 = dec ? FDIM : HDIM;
    const float* bih = dec ? db_ih : eb_ih;
    const float* bhh = dec ? db_hh : eb_hh;
    const float bi = bih[u]          + bhh[u];
    const float bf = bih[u + U2]     + bhh[u + U2];
    const float bg = bih[u + 2 * U2] + bhh[u + 2 * U2];
    const float bo = bih[u + 3 * U2] + bhh[u + 3 * U2];

    // ---- init ----
    for (int i = tid; i < SMEMN; i += NTHR) sm[i] = 0.0f;
    __syncthreads();
    float x_w = 0.0f;   // x(it+1), written into XHE(wb) each enc step
    if (!dec && u < 32) {   // enc threads own the x pipeline: (row q, feat u)
        sm[OFF_XHE(0) + q * XHP + u] =
            x[((size_t)(b0 + q) * T_STEPS + 0) * FDIM + u];
        x_w = x[((size_t)(b0 + q) * T_STEPS + 1) * FDIM + u];
    }
    __syncthreads();

    // row offsets in permuted order (q^l)
    const int ro0 = (q)     * XHP;
    const int ro1 = (q ^ 1) * XHP;
    const int ro2 = (q ^ 2) * XHP;
    const int ro3 = (q ^ 3) * XHP;

    float c_st = 0.0f;

    // 4-row FMA + butterfly reduce for this thread's k-quarter
    auto gates4 = [&](const float* xh, float& gi, float& gf, float& gg, float& go) {
        float aI[4], aF[4], aG[4], aO[4];
        #define DO_ROW(L, RO)                                            \
        {                                                                \
            const ulonglong2* hp =                                       \
                reinterpret_cast<const ulonglong2*>(xh + (RO));          \
            ull cI = 0ull, cF = 0ull, cG = 0ull, cO = 0ull;              \
            _Pragma("unroll")                                            \
            for (int c = 0; c < 6; ++c) {                                \
                ulonglong2 v = hp[c];                                    \
                cI = ffma2(wI[2 * c], v.x, cI);                          \
                cF = ffma2(wF[2 * c], v.x, cF);                          \
                cG = ffma2(wG[2 * c], v.x, cG);                          \
                cO = ffma2(wO[2 * c], v.x, cO);                          \
                cI = ffma2(wI[2 * c + 1], v.y, cI);                      \
                cF = ffma2(wF[2 * c + 1], v.y, cF);                      \
                cG = ffma2(wG[2 * c + 1], v.y, cG);                      \
                cO = ffma2(wO[2 * c + 1], v.y, cO);                      \
            }                                                            \
            aI[L] = hsum2(cI); aF[L] = hsum2(cF);                        \
            aG[L] = hsum2(cG); aO[L] = hsum2(cO);                        \
        }
        DO_ROW(0, ro0)
        DO_ROW(1, ro1)
        DO_ROW(2, ro2)
        DO_ROW(3, ro3)
        #undef DO_ROW
        #define REDUCE(A, OUTV)                                          \
        {                                                                \
            float t0 = A[0] + __shfl_xor_sync(0xFFFFFFFFu, A[1], 1);     \
            float t1 = A[2] + __shfl_xor_sync(0xFFFFFFFFu, A[3], 1);     \
            OUTV = t0 + __shfl_xor_sync(0xFFFFFFFFu, t1, 2);             \
        }
        REDUCE(aI, gi) REDUCE(aF, gf) REDUCE(aG, gg) REDUCE(aO, go)
        #undef REDUCE
    };

    if (!dec) {
        // ================= ENCODER group (warps 0-7) =================
        int s = 0;                       // it % 3
        for (int it = 0; it < T_STEPS; ++it) {
            const int rb = it & 1, wb = rb ^ 1;
            // credit for XHD slot s + enc-internal separation
            BAR_SYNC(1 + s, 384);

            float gi, gf, gg, go;
            gates4(sm + OFF_XHE(rb) + kb, gi, gf, gg, go);
            gi += bi; gf += bf; gg += bg; go += bo;
            float iv = sigf(gi), fv = sigf(gf);
            float gv = tanh_fast(gg), ov = sigf(go);
            c_st = fv * c_st + iv * gv;
            float hv = ov * tanh_fast(c_st);

            sm[OFF_XHE(wb) + q * XHP + FDIM + u] = hv;  // enc recurrence
            sm[OFF_XHD(s)  + q * XHP + u]        = hv;  // h_enc(it) for dec
            if (u < 32) {                               // x(it+1) for step it+1
                sm[OFF_XHE(wb) + q * XHP + u] = x_w;
                if (it + 2 < T_STEPS)
                    x_w = x[((size_t)(b0 + q) * T_STEPS + (it + 2)) * FDIM + u];
            }
            BAR_ARRIVE(4 + s, 384);       // h_enc(it) ready
            if (++s == 3) s = 0;
        }
    } else {
        // ================= DECODER group (warps 8-11) =================
        // prime the credit barriers (slots 0,1,2 free)
        BAR_ARRIVE(1, 384);
        BAR_ARRIVE(2, 384);
        BAR_ARRIVE(3, 384);
        int s = 0;                        // d % 3
        for (int d = 0; d < T_STEPS; ++d) {
            BAR_SYNC(4 + s, 384);         // wait h_enc(d); also dec-internal

            float gi, gf, gg, go;
            gates4(sm + OFF_XHD(s) + kb, gi, gf, gg, go);
            gi += bi; gf += bf; gg += bg; go += bo;
            float iv = sigf(gi), fv = sigf(gf);
            float gv = tanh_fast(gg), ov = sigf(go);
            c_st = fv * c_st + iv * gv;
            float hv = ov * tanh_fast(c_st);

            const int sn = (s == 2) ? 0 : s + 1;
            sm[OFF_XHD(sn) + q * XHP + HDIM + u] = hv;  // h_dec(d) for step d+1
            out[((size_t)(b0 + q) * T_STEPS + d) * FDIM + u] = hv;

            BAR_ARRIVE(1 + s, 384);       // slot s consumed (credit to enc)
            s = sn;
        }
    }
}

extern "C" void kernel_launch(void* const* d_in, const int* in_sizes, int n_in,
                              void* d_out, int out_size)
{
    (void)in_sizes; (void)n_in; (void)out_size;
    lstm_ae_kernel<<<NBLK, NTHR>>>(
        (const float*)d_in[0],
        (const float*)d_in[1], (const float*)d_in[2],
        (const float*)d_in[3], (const float*)d_in[4],
        (const float*)d_in[5], (const float*)d_in[6],
        (const float*)d_in[7], (const float*)d_in[8],
        (float*)d_out);
}

// round 10
// speedup vs baseline: 1.6975x; 1.1181x over previous
#include <cuda_runtime.h>

// LSTM autoencoder: enc (F=32 -> H=64), dec (H=64 -> F=32), B=512, T=1024.
// 128 blocks x 384 threads, 4 batch rows/block.
// tid = pg*8 + s: pg = unit-PAIR (0..31 enc pairs, 32..47 dec pairs),
//                 s  = k-eighth lane [0,8).
// Thread owns 8 gates (2 units x i,f,g,o) over k-eighth [12s,12s+12).
// Weights packed GATE-PAIRWISE: chain0=(I,F)A chain1=(G,O)A chain2=(I,F)B
// chain3=(G,O)B, 4 ull chains x 12 k = 48 ull regs. hv is broadcast-duplicated
// (pk(h,h), alu mov) so each ffma2 accumulates 2 gates at once and hsum2 is
// eliminated. LDS: 3 x LDS.128 per row (12 floats) -> 73 KB/SM/step crossbar
// (half of R7). Row-permuted slots l: acc(row (s^l)&3); reduction = packed
// butterfly xor1/xor2/xor4 (16 add.f32x2 + 32 shfl.b32), interleaved with row
// FMA to shorten live ranges. After reduction lane s holds complete i,f,g,o
// of unit (s>>2) of its pair for row s&3 -> non-redundant elementwise.
// XHP=104: bank base 8*((s^l)&3)+12s distinct mod 32 for all l -> conflict-free.
// Double-buffered xh, ONE __syncthreads/step, decoder lags encoder by 1 step.

#define T_STEPS 1024
#define FDIM    32
#define HDIM    64
#define ROWS    4
#define NBLK    128
#define NTHR    384
#define XHP     104

#define OFF_XHE(b) ((b) * (ROWS * XHP))
#define OFF_XHD(b) (2 * ROWS * XHP + (b) * (ROWS * XHP))
#define SMEMN      (4 * ROWS * XHP)

typedef unsigned long long ull;
union U64F2 { ull u; float2 f; };

__device__ __forceinline__ ull pk(float lo, float hi) {
    U64F2 u; u.f = make_float2(lo, hi); return u.u;
}
__device__ __forceinline__ ull ffma2(ull a, ull b, ull c) {
    ull d;
    asm("fma.rn.f32x2 %0, %1, %2, %3;" : "=l"(d) : "l"(a), "l"(b), "l"(c));
    return d;
}
__device__ __forceinline__ ull padd2(ull a, ull b) {
    ull d;
    asm("add.rn.f32x2 %0, %1, %2;" : "=l"(d) : "l"(a), "l"(b));
    return d;
}
__device__ __forceinline__ ull shx64(ull v, int m) {
    return __shfl_xor_sync(0xFFFFFFFFu, v, m);
}
__device__ __forceinline__ float sigf(float x) {
    return __fdividef(1.0f, 1.0f + __expf(-x));
}
__device__ __forceinline__ float tanh_fast(float x) {
    float e = __expf(2.0f * x);
    return 1.0f - __fdividef(2.0f, e + 1.0f);
}

__global__ void __launch_bounds__(NTHR, 1) lstm_ae_kernel(
    const float* __restrict__ x,
    const float* __restrict__ ew_ih, const float* __restrict__ ew_hh,
    const float* __restrict__ eb_ih, const float* __restrict__ eb_hh,
    const float* __restrict__ dw_ih, const float* __restrict__ dw_hh,
    const float* __restrict__ db_ih, const float* __restrict__ db_hh,
    float* __restrict__ out)
{
    __shared__ __align__(16) float sm[SMEMN];
    const int tid = threadIdx.x;
    const int b0  = blockIdx.x * ROWS;

    const int pg   = tid >> 3;            // unit-pair 0..47 (warp = 4 pairs)
    const bool dec = (pg >= 32);
    const int pp   = dec ? (pg - 32) : pg;
    const int s    = tid & 7;             // k-eighth lane
    const int uu   = (s >> 2) & 1;        // which unit of the pair I handle in ew
    const int row  = s & 3;               // my elementwise row
    const int kb   = 12 * s;
    const int uA   = 2 * pp;              // pair's units within its lstm
    const int U    = uA + uu;             // my ew unit

    // ---- weights -> registers, packed gate-pairwise ----
    ull w0[12], w1[12], w2[12], w3[12];
    {
        const int NU = dec ? FDIM : HDIM;
        const int KI = dec ? HDIM : FDIM;
        const int KH = dec ? FDIM : HDIM;
        const float* wih = dec ? dw_ih : ew_ih;
        const float* whh = dec ? dw_hh : ew_hh;
        #define WV(G, K) ((K) < KI ? wih[(G) * KI + (K)] : whh[(G) * KH + ((K) - KI)])
        #pragma unroll
        for (int j = 0; j < 12; ++j) {
            const int k = kb + j;
            w0[j] = pk(WV(uA, k),             WV(uA + NU, k));       // (I,F) unit A
            w1[j] = pk(WV(uA + 2 * NU, k),    WV(uA + 3 * NU, k));   // (G,O) unit A
            w2[j] = pk(WV(uA + 1, k),         WV(uA + 1 + NU, k));   // (I,F) unit B
            w3[j] = pk(WV(uA + 1 + 2 * NU, k), WV(uA + 1 + 3 * NU, k)); // (G,O) B
        }
        #undef WV
    }

    // ---- biases for my ew unit ----
    const int NU2 = dec ? FDIM : HDIM;
    const float* bih = dec ? db_ih : eb_ih;
    const float* bhh = dec ? db_hh : eb_hh;
    const float bi = bih[U]           + bhh[U];
    const float bf = bih[U + NU2]     + bhh[U + NU2];
    const float bg = bih[U + 2 * NU2] + bhh[U + 2 * NU2];
    const float bo = bih[U + 3 * NU2] + bhh[U + 3 * NU2];

    // ---- init state; x(0); prefetch x(1). dec lanes cover 4x32 x-slots ----
    for (int i = tid; i < SMEMN; i += NTHR) sm[i] = 0.0f;
    __syncthreads();
    float x_pref = 0.0f;
    if (dec) {
        sm[OFF_XHE(0) + row * XHP + U] =
            x[((size_t)(b0 + row) * T_STEPS + 0) * FDIM + U];
        x_pref = x[((size_t)(b0 + row) * T_STEPS + 1) * FDIM + U];
    }
    __syncthreads();

    // row offsets in permuted slot order (s^l)&3
    const int ro0 = ((s)     & 3) * XHP;
    const int ro1 = ((s ^ 1) & 3) * XHP;
    const int ro2 = ((s ^ 2) & 3) * XHP;
    const int ro3 = ((s ^ 3) & 3) * XHP;

    float c_st = 0.0f;

    for (int it = 0; it <= T_STEPS; ++it) {
        const int rb = it & 1, wb = rb ^ 1;
        const bool live = dec ? (it > 0) : (it < T_STEPS);
        const float* xh = sm + (dec ? OFF_XHD(rb) : OFF_XHE(rb)) + kb;

        // ===== FMA on 4 rows, gate-pair packed; reduce incrementally =====
        #define KS(J, F)                                                     \
        {                                                                    \
            ull hd = pk(F, F);                                               \
            c0 = ffma2(w0[J], hd, c0);                                       \
            c1 = ffma2(w1[J], hd, c1);                                       \
            c2 = ffma2(w2[J], hd, c2);                                       \
            c3 = ffma2(w3[J], hd, c3);                                       \
        }
        #define DO_ROW(RO, O0, O1, O2, O3)                                   \
        {                                                                    \
            const float4* hp = reinterpret_cast<const float4*>(xh + (RO));   \
            float4 v0 = hp[0], v1 = hp[1], v2 = hp[2];                       \
            ull c0 = 0ull, c1 = 0ull, c2 = 0ull, c3 = 0ull;                  \
            KS(0, v0.x) KS(1, v0.y) KS(2, v0.z) KS(3, v0.w)                  \
            KS(4, v1.x) KS(5, v1.y) KS(6, v1.z) KS(7, v1.w)                  \
            KS(8, v2.x) KS(9, v2.y) KS(10, v2.z) KS(11, v2.w)                \
            O0 = c0; O1 = c1; O2 = c2; O3 = c3;                              \
        }
        ull p0, p1, p2, p3, q0, q1, q2, q3;
        ull t0, t1, t2, t3;
        DO_ROW(ro0, p0, p1, p2, p3)           // slot 0: row s&3
        DO_ROW(ro1, q0, q1, q2, q3)           // slot 1: row (s^1)&3
        t0 = padd2(p0, shx64(q0, 1));         // row s&3 over eighths {s,s^1}
        t1 = padd2(p1, shx64(q1, 1));
        t2 = padd2(p2, shx64(q2, 1));
        t3 = padd2(p3, shx64(q3, 1));
        DO_ROW(ro2, p0, p1, p2, p3)           // slot 2: row (s^2)&3
        DO_ROW(ro3, q0, q1, q2, q3)           // slot 3: row (s^3)&3
        p0 = padd2(p0, shx64(q0, 1));         // row (s^2)&3 over {s,s^1}
        p1 = padd2(p1, shx64(q1, 1));
        p2 = padd2(p2, shx64(q2, 1));
        p3 = padd2(p3, shx64(q3, 1));
        t0 = padd2(t0, shx64(p0, 2));         // row s&3 over {s..s^3}
        t1 = padd2(t1, shx64(p1, 2));
        t2 = padd2(t2, shx64(p2, 2));
        t3 = padd2(t3, shx64(p3, 2));
        t0 = padd2(t0, shx64(t0, 4));         // row s&3 over all 8 eighths
        t1 = padd2(t1, shx64(t1, 4));
        t2 = padd2(t2, shx64(t2, 4));
        t3 = padd2(t3, shx64(t3, 4));
        #undef DO_ROW
        #undef KS

        // select my unit's (I,F) and (G,O) packed sums
        ull cIF = uu ? t2 : t0;
        ull cGO = uu ? t3 : t1;
        U64F2 uf; float gi, gf, gg, go;
        uf.u = cIF; gi = uf.f.x + bi; gf = uf.f.y + bf;
        uf.u = cGO; gg = uf.f.x + bg; go = uf.f.y + bo;

        // ===== elementwise: thread owns (unit U, row) =====
        if (live) {
            float iv = sigf(gi), fv = sigf(gf);
            float gv = tanh_fast(gg), ov = sigf(go);
            c_st = fv * c_st + iv * gv;
            float hv = ov * tanh_fast(c_st);
            if (!dec) {
                sm[OFF_XHE(wb) + row * XHP + FDIM + U] = hv;  // enc recurrence
                sm[OFF_XHD(wb) + row * XHP + U]        = hv;  // dec input
            } else {
                sm[OFF_XHD(wb) + row * XHP + HDIM + U] = hv;  // dec recurrence
                out[((size_t)(b0 + row) * T_STEPS + (it - 1)) * FDIM + U] = hv;
            }
        }
        if (dec) {   // x pipeline
            if (it + 1 < T_STEPS)
                sm[OFF_XHE(wb) + row * XHP + U] = x_pref;
            if (it + 2 < T_STEPS)
                x_pref = x[((size_t)(b0 + row) * T_STEPS + (it + 2)) * FDIM + U];
        }
        __syncthreads();
    }
}

extern "C" void kernel_launch(void* const* d_in, const int* in_sizes, int n_in,
                              void* d_out, int out_size)
{
    (void)in_sizes; (void)n_in; (void)out_size;
    lstm_ae_kernel<<<NBLK, NTHR>>>(
        (const float*)d_in[0],
        (const float*)d_in[1], (const float*)d_in[2],
        (const float*)d_in[3], (const float*)d_in[4],
        (const float*)d_in[5], (const float*)d_in[6],
        (const float*)d_in[7], (const float*)d_in[8],
        (float*)d_out);
}

// round 11
// speedup vs baseline: 1.7167x; 1.0113x over previous
#include <cuda_runtime.h>

// LSTM autoencoder: enc (F=32 -> H=64), dec (H=64 -> F=32), B=512, T=1024.
// 128 blocks x 384 threads, 4 batch rows/block.
// tid = pg*8 + s: pg = unit-PAIR (0..31 enc, 32..47 dec), s = k-eighth lane.
// Thread owns 8 gates (2 units x i,f,g,o) over k-eighth [12s,12s+12),
// weights packed gate-pairwise in 4 ull chains x 12 (ffma2 does 2 gates/op).
// ACTIVATION SCALES FOLDED INTO WEIGHTS: i,f,o chains pre-scaled by -log2e,
// g chains by +2*log2e -> sigmoid = rcp(1+ex2(g)), tanh = fma(-2,rcp(ex2(g)+1),1)
// with zero pre-multiplies. BIASES FOLDED INTO FMA: lane 0 initializes its
// accumulator chains with the packed (pre-scaled) biases; lane0's slot-l chain
// is row l's unique contribution so each bias lands exactly once.
// Reduction: packed butterfly xor1/xor2 then an xor4 EXCHANGE (each lane keeps
// its own unit's sums and receives the partner-needed value: 14 shx64 total).
// XHP=104: bank base 8*((s^l)&3)+12s distinct mod 32 -> conflict-free LDS.128.
// Double-buffered xh, ONE __syncthreads/step, decoder lags encoder 1 step.

#define T_STEPS 1024
#define FDIM    32
#define HDIM    64
#define ROWS    4
#define NBLK    128
#define NTHR    384
#define XHP     104

#define OFF_XHE(b) ((b) * (ROWS * XHP))
#define OFF_XHD(b) (2 * ROWS * XHP + (b) * (ROWS * XHP))
#define SMEMN      (4 * ROWS * XHP)

#define L2E  1.4426950408889634f

typedef unsigned long long ull;
union U64F2 { ull u; float2 f; };

__device__ __forceinline__ ull pk(float lo, float hi) {
    U64F2 u; u.f = make_float2(lo, hi); return u.u;
}
__device__ __forceinline__ ull ffma2(ull a, ull b, ull c) {
    ull d;
    asm("fma.rn.f32x2 %0, %1, %2, %3;" : "=l"(d) : "l"(a), "l"(b), "l"(c));
    return d;
}
__device__ __forceinline__ ull padd2(ull a, ull b) {
    ull d;
    asm("add.rn.f32x2 %0, %1, %2;" : "=l"(d) : "l"(a), "l"(b));
    return d;
}
__device__ __forceinline__ ull shx64(ull v, int m) {
    return __shfl_xor_sync(0xFFFFFFFFu, v, m);
}
__device__ __forceinline__ float ex2f(float x) {
    float r; asm("ex2.approx.f32 %0, %1;" : "=f"(r) : "f"(x)); return r;
}
__device__ __forceinline__ float rcpf(float x) {
    float r; asm("rcp.approx.f32 %0, %1;" : "=f"(r) : "f"(x)); return r;
}
// input pre-scaled by -log2e: sigmoid(x) = 1/(1 + 2^(-x*log2e))
__device__ __forceinline__ float sig_pre(float g) {
    return rcpf(1.0f + ex2f(g));
}
// input pre-scaled by +2*log2e: tanh(x) = 1 - 2/(2^(2x*log2e) + 1)
__device__ __forceinline__ float tanh_pre(float g) {
    return fmaf(-2.0f, rcpf(ex2f(g) + 1.0f), 1.0f);
}
__device__ __forceinline__ float tanh_raw(float c) {
    return tanh_pre(c * (2.0f * L2E));
}

__global__ void __launch_bounds__(NTHR, 1) lstm_ae_kernel(
    const float* __restrict__ x,
    const float* __restrict__ ew_ih, const float* __restrict__ ew_hh,
    const float* __restrict__ eb_ih, const float* __restrict__ eb_hh,
    const float* __restrict__ dw_ih, const float* __restrict__ dw_hh,
    const float* __restrict__ db_ih, const float* __restrict__ db_hh,
    float* __restrict__ out)
{
    __shared__ __align__(16) float sm[SMEMN];
    const int tid = threadIdx.x;
    const int b0  = blockIdx.x * ROWS;

    const int pg   = tid >> 3;            // unit-pair 0..47 (warp = 4 pairs)
    const bool dec = (pg >= 32);
    const int pp   = dec ? (pg - 32) : pg;
    const int s    = tid & 7;             // k-eighth lane
    const int uu   = (s >> 2) & 1;        // my ew unit within the pair
    const int row  = s & 3;               // my elementwise row
    const int kb   = 12 * s;
    const int uA   = 2 * pp;
    const int U    = uA + uu;

    // ---- weights -> registers, gate-pair packed, ACTIVATION SCALES FOLDED ----
    ull w0[12], w1[12], w2[12], w3[12];
    {
        const int NU = dec ? FDIM : HDIM;
        const int KI = dec ? HDIM : FDIM;
        const int KH = dec ? FDIM : HDIM;
        const float* wih = dec ? dw_ih : ew_ih;
        const float* whh = dec ? dw_hh : ew_hh;
        #define WV(G, K) ((K) < KI ? wih[(G) * KI + (K)] : whh[(G) * KH + ((K) - KI)])
        #pragma unroll
        for (int j = 0; j < 12; ++j) {
            const int k = kb + j;
            w0[j] = pk(-L2E * WV(uA, k),                 -L2E * WV(uA + NU, k));
            w1[j] = pk(2.0f * L2E * WV(uA + 2 * NU, k),  -L2E * WV(uA + 3 * NU, k));
            w2[j] = pk(-L2E * WV(uA + 1, k),             -L2E * WV(uA + 1 + NU, k));
            w3[j] = pk(2.0f * L2E * WV(uA + 1 + 2 * NU, k), -L2E * WV(uA + 1 + 3 * NU, k));
        }
        #undef WV
    }

    // ---- packed pre-scaled biases, carried only on lane s==0 ----
    ull bIFa = 0ull, bGOa = 0ull, bIFb = 0ull, bGOb = 0ull;
    {
        const int NU = dec ? FDIM : HDIM;
        const float* bih = dec ? db_ih : eb_ih;
        const float* bhh = dec ? db_hh : eb_hh;
        if (s == 0) {
            #define BV(G) (bih[G] + bhh[G])
            bIFa = pk(-L2E * BV(uA),                -L2E * BV(uA + NU));
            bGOa = pk(2.0f * L2E * BV(uA + 2 * NU), -L2E * BV(uA + 3 * NU));
            bIFb = pk(-L2E * BV(uA + 1),            -L2E * BV(uA + 1 + NU));
            bGOb = pk(2.0f * L2E * BV(uA + 1 + 2 * NU), -L2E * BV(uA + 1 + 3 * NU));
            #undef BV
        }
    }

    // ---- init state; x(0); prefetch x(1). dec lanes cover 4x32 x-slots ----
    for (int i = tid; i < SMEMN; i += NTHR) sm[i] = 0.0f;
    __syncthreads();
    const float* xp = x + ((size_t)(b0 + row) * T_STEPS) * FDIM + U;  // dec only
    float* outp = out + ((size_t)(b0 + row) * T_STEPS) * FDIM + U;    // dec only
    float x_pref = 0.0f;
    if (dec) {
        sm[OFF_XHE(0) + row * XHP + U] = xp[0];
        x_pref = xp[FDIM];
        xp += 2 * FDIM;   // points at x(2)
    }
    __syncthreads();

    // row offsets in permuted slot order (s^l)&3
    const int ro0 = ((s)     & 3) * XHP;
    const int ro1 = ((s ^ 1) & 3) * XHP;
    const int ro2 = ((s ^ 2) & 3) * XHP;
    const int ro3 = ((s ^ 3) & 3) * XHP;

    float c_st = 0.0f;

    for (int it = 0; it <= T_STEPS; ++it) {
        const int rb = it & 1, wb = rb ^ 1;
        const bool live = dec ? (it > 0) : (it < T_STEPS);
        const float* xh = sm + (dec ? OFF_XHD(rb) : OFF_XHE(rb)) + kb;

        // ===== FMA on 4 rows, gate-pair packed; biases init lane0 chains =====
        #define KS(J, F)                                                     \
        {                                                                    \
            ull hd = pk(F, F);                                               \
            c0 = ffma2(w0[J], hd, c0);                                       \
            c1 = ffma2(w1[J], hd, c1);                                       \
            c2 = ffma2(w2[J], hd, c2);                                       \
            c3 = ffma2(w3[J], hd, c3);                                       \
        }
        #define DO_ROW(RO, O0, O1, O2, O3)                                   \
        {                                                                    \
            const float4* hp = reinterpret_cast<const float4*>(xh + (RO));   \
            float4 v0 = hp[0], v1 = hp[1], v2 = hp[2];                       \
            ull c0 = bIFa, c1 = bGOa, c2 = bIFb, c3 = bGOb;                  \
            KS(0, v0.x) KS(1, v0.y) KS(2, v0.z) KS(3, v0.w)                  \
            KS(4, v1.x) KS(5, v1.y) KS(6, v1.z) KS(7, v1.w)                  \
            KS(8, v2.x) KS(9, v2.y) KS(10, v2.z) KS(11, v2.w)                \
            O0 = c0; O1 = c1; O2 = c2; O3 = c3;                              \
        }
        ull p0, p1, p2, p3, q0, q1, q2, q3;
        ull t0, t1, t2, t3;
        DO_ROW(ro0, p0, p1, p2, p3)           // slot 0: row s&3
        DO_ROW(ro1, q0, q1, q2, q3)           // slot 1: row (s^1)&3
        t0 = padd2(p0, shx64(q0, 1));
        t1 = padd2(p1, shx64(q1, 1));
        t2 = padd2(p2, shx64(q2, 1));
        t3 = padd2(p3, shx64(q3, 1));
        DO_ROW(ro2, p0, p1, p2, p3)           // slot 2: row (s^2)&3
        DO_ROW(ro3, q0, q1, q2, q3)           // slot 3: row (s^3)&3
        p0 = padd2(p0, shx64(q0, 1));
        p1 = padd2(p1, shx64(q1, 1));
        p2 = padd2(p2, shx64(q2, 1));
        p3 = padd2(p3, shx64(q3, 1));
        t0 = padd2(t0, shx64(p0, 2));         // row s&3 over lanes {s..s^3}
        t1 = padd2(t1, shx64(p1, 2));
        t2 = padd2(t2, shx64(p2, 2));
        t3 = padd2(t3, shx64(p3, 2));
        #undef DO_ROW
        #undef KS

        // ===== xor4 EXCHANGE: keep my unit's sums, receive partner's need =====
        ull keepIF = uu ? t2 : t0;
        ull keepGO = uu ? t3 : t1;
        ull sendIF = uu ? t0 : t2;
        ull sendGO = uu ? t1 : t3;
        ull cIF = padd2(keepIF, shx64(sendIF, 4));
        ull cGO = padd2(keepGO, shx64(sendGO, 4));

        U64F2 uf; float gi, gf, gg, go;
        uf.u = cIF; gi = uf.f.x; gf = uf.f.y;   // pre-scaled by -log2e
        uf.u = cGO; gg = uf.f.x; go = uf.f.y;   // gg: +2log2e, go: -log2e

        // ===== elementwise: thread owns (unit U, row) =====
        if (live) {
            float iv = sig_pre(gi), fv = sig_pre(gf);
            float gv = tanh_pre(gg), ov = sig_pre(go);
            c_st = fv * c_st + iv * gv;
            float hv = ov * tanh_raw(c_st);
            if (!dec) {
                sm[OFF_XHE(wb) + row * XHP + FDIM + U] = hv;  // enc recurrence
                sm[OFF_XHD(wb) + row * XHP + U]        = hv;  // dec input
            } else {
                sm[OFF_XHD(wb) + row * XHP + HDIM + U] = hv;  // dec recurrence
                *outp = hv;
                outp += FDIM;
            }
        }
        if (dec) {   // x pipeline
            if (it + 1 < T_STEPS)
                sm[OFF_XHE(wb) + row * XHP + U] = x_pref;
            if (it + 2 < T_STEPS) {
                x_pref = *xp;
                xp += FDIM;
            }
        }
        __syncthreads();
    }
}

extern "C" void kernel_launch(void* const* d_in, const int* in_sizes, int n_in,
                              void* d_out, int out_size)
{
    (void)in_sizes; (void)n_in; (void)out_size;
    lstm_ae_kernel<<<NBLK, NTHR>>>(
        (const float*)d_in[0],
        (const float*)d_in[1], (const float*)d_in[2],
        (const float*)d_in[3], (const float*)d_in[4],
        (const float*)d_in[5], (const float*)d_in[6],
        (const float*)d_in[7], (const float*)d_in[8],
        (float*)d_out);
}

// round 12
// speedup vs baseline: 1.8148x; 1.0571x over previous
#include <cuda_runtime.h>

// LSTM autoencoder: enc (F=32 -> H=64), dec (H=64 -> F=32), B=512, T=1024.
// 128 blocks x 384 threads, 4 batch rows/block.
// tid = pg*8 + s: pg = unit-PAIR (0..31 enc, 32..47 dec), s = k-eighth lane.
// Thread owns 8 gates (2 units x i,f,g,o) over k-eighth [12s,12s+12),
// weights packed gate-pairwise in 4 ull chains x 12 (ffma2 does 2 gates/op).
// Gate scales folded into weights/biases:
//   i,f chains: -log2e  -> sigmoid = rcp(1 + ex2(g))      (exact path, feeds c)
//   g chains:    1.0    -> tanh.approx.f32 directly        (HW tanh, 1 MUFU)
//   o chains:    0.5    -> sigmoid = fma(0.5, tanh_hw(g), 0.5)
//   tanh(c):     tanh.approx.f32 direct (no pre-scale)
// MUFU per ew: 7 (was 10) -> smaller serialized MUFU burst in the post-reduce
// tail. Biases folded into lane-0 accumulator init (slot l = row l's unique
// contribution). Reduction: packed butterfly xor1/xor2 + xor4 exchange
// (14 shx64). XHP=104: bank base 8*((s^l)&3)+12s distinct mod 32 ->
// conflict-free LDS.128. Double-buffered xh, ONE __syncthreads/step,
// decoder lags encoder by 1 step. Pointer-bumped x/out addressing.

#define T_STEPS 1024
#define FDIM    32
#define HDIM    64
#define ROWS    4
#define NBLK    128
#define NTHR    384
#define XHP     104

#define OFF_XHE(b) ((b) * (ROWS * XHP))
#define OFF_XHD(b) (2 * ROWS * XHP + (b) * (ROWS * XHP))
#define SMEMN      (4 * ROWS * XHP)

#define L2E  1.4426950408889634f

typedef unsigned long long ull;
union U64F2 { ull u; float2 f; };

__device__ __forceinline__ ull pk(float lo, float hi) {
    U64F2 u; u.f = make_float2(lo, hi); return u.u;
}
__device__ __forceinline__ ull ffma2(ull a, ull b, ull c) {
    ull d;
    asm("fma.rn.f32x2 %0, %1, %2, %3;" : "=l"(d) : "l"(a), "l"(b), "l"(c));
    return d;
}
__device__ __forceinline__ ull padd2(ull a, ull b) {
    ull d;
    asm("add.rn.f32x2 %0, %1, %2;" : "=l"(d) : "l"(a), "l"(b));
    return d;
}
__device__ __forceinline__ ull shx64(ull v, int m) {
    return __shfl_xor_sync(0xFFFFFFFFu, v, m);
}
__device__ __forceinline__ float ex2f(float x) {
    float r; asm("ex2.approx.f32 %0, %1;" : "=f"(r) : "f"(x)); return r;
}
__device__ __forceinline__ float rcpf(float x) {
    float r; asm("rcp.approx.f32 %0, %1;" : "=f"(r) : "f"(x)); return r;
}
__device__ __forceinline__ float tanh_hw(float x) {
    float r; asm("tanh.approx.f32 %0, %1;" : "=f"(r) : "f"(x)); return r;
}
// input pre-scaled by -log2e: sigmoid(x) = 1/(1 + 2^(-x*log2e))  (exact path)
__device__ __forceinline__ float sig_pre(float g) {
    return rcpf(1.0f + ex2f(g));
}

__global__ void __launch_bounds__(NTHR, 1) lstm_ae_kernel(
    const float* __restrict__ x,
    const float* __restrict__ ew_ih, const float* __restrict__ ew_hh,
    const float* __restrict__ eb_ih, const float* __restrict__ eb_hh,
    const float* __restrict__ dw_ih, const float* __restrict__ dw_hh,
    const float* __restrict__ db_ih, const float* __restrict__ db_hh,
    float* __restrict__ out)
{
    __shared__ __align__(16) float sm[SMEMN];
    const int tid = threadIdx.x;
    const int b0  = blockIdx.x * ROWS;

    const int pg   = tid >> 3;            // unit-pair 0..47 (warp = 4 pairs)
    const bool dec = (pg >= 32);
    const int pp   = dec ? (pg - 32) : pg;
    const int s    = tid & 7;             // k-eighth lane
    const int uu   = (s >> 2) & 1;        // my ew unit within the pair
    const int row  = s & 3;               // my elementwise row
    const int kb   = 12 * s;
    const int uA   = 2 * pp;
    const int U    = uA + uu;

    // ---- weights -> registers, gate-pair packed, gate scales folded ----
    ull w0[12], w1[12], w2[12], w3[12];
    {
        const int NU = dec ? FDIM : HDIM;
        const int KI = dec ? HDIM : FDIM;
        const int KH = dec ? FDIM : HDIM;
        const float* wih = dec ? dw_ih : ew_ih;
        const float* whh = dec ? dw_hh : ew_hh;
        #define WV(G, K) ((K) < KI ? wih[(G) * KI + (K)] : whh[(G) * KH + ((K) - KI)])
        #pragma unroll
        for (int j = 0; j < 12; ++j) {
            const int k = kb + j;
            w0[j] = pk(-L2E * WV(uA, k),          -L2E * WV(uA + NU, k));       // (I,F) A
            w1[j] = pk(WV(uA + 2 * NU, k),        0.5f * WV(uA + 3 * NU, k));   // (G,O) A
            w2[j] = pk(-L2E * WV(uA + 1, k),      -L2E * WV(uA + 1 + NU, k));   // (I,F) B
            w3[j] = pk(WV(uA + 1 + 2 * NU, k),    0.5f * WV(uA + 1 + 3 * NU, k)); // (G,O) B
        }
        #undef WV
    }

    // ---- packed pre-scaled biases, carried only on lane s==0 ----
    ull bIFa = 0ull, bGOa = 0ull, bIFb = 0ull, bGOb = 0ull;
    {
        const int NU = dec ? FDIM : HDIM;
        const float* bih = dec ? db_ih : eb_ih;
        const float* bhh = dec ? db_hh : eb_hh;
        if (s == 0) {
            #define BV(G) (bih[G] + bhh[G])
            bIFa = pk(-L2E * BV(uA),            -L2E * BV(uA + NU));
            bGOa = pk(BV(uA + 2 * NU),          0.5f * BV(uA + 3 * NU));
            bIFb = pk(-L2E * BV(uA + 1),        -L2E * BV(uA + 1 + NU));
            bGOb = pk(BV(uA + 1 + 2 * NU),      0.5f * BV(uA + 1 + 3 * NU));
            #undef BV
        }
    }

    // ---- init state; x(0); prefetch x(1). dec lanes cover 4x32 x-slots ----
    for (int i = tid; i < SMEMN; i += NTHR) sm[i] = 0.0f;
    __syncthreads();
    const float* xp = x + ((size_t)(b0 + row) * T_STEPS) * FDIM + U;  // dec only
    float* outp = out + ((size_t)(b0 + row) * T_STEPS) * FDIM + U;    // dec only
    float x_pref = 0.0f;
    if (dec) {
        sm[OFF_XHE(0) + row * XHP + U] = xp[0];
        x_pref = xp[FDIM];
        xp += 2 * FDIM;   // points at x(2)
    }
    __syncthreads();

    // row offsets in permuted slot order (s^l)&3
    const int ro0 = ((s)     & 3) * XHP;
    const int ro1 = ((s ^ 1) & 3) * XHP;
    const int ro2 = ((s ^ 2) & 3) * XHP;
    const int ro3 = ((s ^ 3) & 3) * XHP;

    float c_st = 0.0f;

    for (int it = 0; it <= T_STEPS; ++it) {
        const int rb = it & 1, wb = rb ^ 1;
        const bool live = dec ? (it > 0) : (it < T_STEPS);
        const float* xh = sm + (dec ? OFF_XHD(rb) : OFF_XHE(rb)) + kb;

        // ===== FMA on 4 rows, gate-pair packed; biases init lane0 chains =====
        #define KS(J, F)                                                     \
        {                                                                    \
            ull hd = pk(F, F);                                               \
            c0 = ffma2(w0[J], hd, c0);                                       \
            c1 = ffma2(w1[J], hd, c1);                                       \
            c2 = ffma2(w2[J], hd, c2);                                       \
            c3 = ffma2(w3[J], hd, c3);                                       \
        }
        #define DO_ROW(RO, O0, O1, O2, O3)                                   \
        {                                                                    \
            const float4* hp = reinterpret_cast<const float4*>(xh + (RO));   \
            float4 v0 = hp[0], v1 = hp[1], v2 = hp[2];                       \
            ull c0 = bIFa, c1 = bGOa, c2 = bIFb, c3 = bGOb;                  \
            KS(0, v0.x) KS(1, v0.y) KS(2, v0.z) KS(3, v0.w)                  \
            KS(4, v1.x) KS(5, v1.y) KS(6, v1.z) KS(7, v1.w)                  \
            KS(8, v2.x) KS(9, v2.y) KS(10, v2.z) KS(11, v2.w)                \
            O0 = c0; O1 = c1; O2 = c2; O3 = c3;                              \
        }
        ull p0, p1, p2, p3, q0, q1, q2, q3;
        ull t0, t1, t2, t3;
        DO_ROW(ro0, p0, p1, p2, p3)           // slot 0: row s&3
        DO_ROW(ro1, q0, q1, q2, q3)           // slot 1: row (s^1)&3
        t0 = padd2(p0, shx64(q0, 1));
        t1 = padd2(p1, shx64(q1, 1));
        t2 = padd2(p2, shx64(q2, 1));
        t3 = padd2(p3, shx64(q3, 1));
        DO_ROW(ro2, p0, p1, p2, p3)           // slot 2: row (s^2)&3
        DO_ROW(ro3, q0, q1, q2, q3)           // slot 3: row (s^3)&3
        p0 = padd2(p0, shx64(q0, 1));
        p1 = padd2(p1, shx64(q1, 1));
        p2 = padd2(p2, shx64(q2, 1));
        p3 = padd2(p3, shx64(q3, 1));
        t0 = padd2(t0, shx64(p0, 2));         // row s&3 over lanes {s..s^3}
        t1 = padd2(t1, shx64(p1, 2));
        t2 = padd2(t2, shx64(p2, 2));
        t3 = padd2(t3, shx64(p3, 2));
        #undef DO_ROW
        #undef KS

        // ===== xor4 EXCHANGE: keep my unit's sums, receive partner's need =====
        ull keepIF = uu ? t2 : t0;
        ull keepGO = uu ? t3 : t1;
        ull sendIF = uu ? t0 : t2;
        ull sendGO = uu ? t1 : t3;
        ull cIF = padd2(keepIF, shx64(sendIF, 4));
        ull cGO = padd2(keepGO, shx64(sendGO, 4));

        U64F2 uf; float gi, gf, gg, go;
        uf.u = cIF; gi = uf.f.x; gf = uf.f.y;   // pre-scaled by -log2e
        uf.u = cGO; gg = uf.f.x; go = uf.f.y;   // gg: x1.0 (tanh), go: x0.5

        // ===== elementwise: thread owns (unit U, row) =====
        if (live) {
            float iv = sig_pre(gi), fv = sig_pre(gf);       // exact (feed c)
            float gv = tanh_hw(gg);                          // HW tanh
            float ov = fmaf(0.5f, tanh_hw(go), 0.5f);        // HW sigmoid
            c_st = fv * c_st + iv * gv;
            float hv = ov * tanh_hw(c_st);                   // HW tanh
            if (!dec) {
                sm[OFF_XHE(wb) + row * XHP + FDIM + U] = hv;  // enc recurrence
                sm[OFF_XHD(wb) + row * XHP + U]        = hv;  // dec input
            } else {
                sm[OFF_XHD(wb) + row * XHP + HDIM + U] = hv;  // dec recurrence
                *outp = hv;
                outp += FDIM;
            }
        }
        if (dec) {   // x pipeline
            if (it + 1 < T_STEPS)
                sm[OFF_XHE(wb) + row * XHP + U] = x_pref;
            if (it + 2 < T_STEPS) {
                x_pref = *xp;
                xp += FDIM;
            }
        }
        __syncthreads();
    }
}

extern "C" void kernel_launch(void* const* d_in, const int* in_sizes, int n_in,
                              void* d_out, int out_size)
{
    (void)in_sizes; (void)n_in; (void)out_size;
    lstm_ae_kernel<<<NBLK, NTHR>>>(
        (const float*)d_in[0],
        (const float*)d_in[1], (const float*)d_in[2],
        (const float*)d_in[3], (const float*)d_in[4],
        (const float*)d_in[5], (const float*)d_in[6],
        (const float*)d_in[7], (const float*)d_in[8],
        (float*)d_out);
}

// round 13
// speedup vs baseline: 1.8996x; 1.0467x over previous
#include <cuda_runtime.h>

// LSTM autoencoder: enc (F=32 -> H=64), dec (H=64 -> F=32), B=512, T=1024.
// 128 blocks x 384 threads, 4 batch rows/block.
// tid = pg*8 + s: pg = unit-PAIR (0..31 enc, 32..47 dec), s = k-eighth lane.
// Thread owns 8 gates (2 units x i,f,g,o) over k-eighth [12s,12s+12),
// weights packed gate-pairwise in 4 ull chains x 12 (ffma2 does 2 gates/op).
// ALL activations on the HW tanh MUFU (5 x tanh.approx per ew, no ex2/rcp):
//   i,f chains pre-scaled 0.5 -> sig = fma(0.5, tanh_hw(g), 0.5)
//   g chains   pre-scaled 1.0 -> tanh_hw(g)
//   o chains   pre-scaled 0.5 -> sig = fma(0.5, tanh_hw(g), 0.5)
//   tanh(c)    tanh_hw(c)
// Biases folded into lane-0 accumulator init (slot l = row l's unique
// contribution). Reduction: packed butterfly xor1/xor2 + xor4 exchange
// (14 shx64). XHP=104: bank base 8*((s^l)&3)+12s distinct mod 32 ->
// conflict-free LDS.128. Double-buffered xh, ONE __syncthreads/step,
// decoder lags encoder by 1 step. First (enc-only) and last (dec-only)
// steps peeled so the steady loop body is predicate-free.

#define T_STEPS 1024
#define FDIM    32
#define HDIM    64
#define ROWS    4
#define NBLK    128
#define NTHR    384
#define XHP     104

#define OFF_XHE(b) ((b) * (ROWS * XHP))
#define OFF_XHD(b) (2 * ROWS * XHP + (b) * (ROWS * XHP))
#define SMEMN      (4 * ROWS * XHP)

typedef unsigned long long ull;
union U64F2 { ull u; float2 f; };

__device__ __forceinline__ ull pk(float lo, float hi) {
    U64F2 u; u.f = make_float2(lo, hi); return u.u;
}
__device__ __forceinline__ ull ffma2(ull a, ull b, ull c) {
    ull d;
    asm("fma.rn.f32x2 %0, %1, %2, %3;" : "=l"(d) : "l"(a), "l"(b), "l"(c));
    return d;
}
__device__ __forceinline__ ull padd2(ull a, ull b) {
    ull d;
    asm("add.rn.f32x2 %0, %1, %2;" : "=l"(d) : "l"(a), "l"(b));
    return d;
}
__device__ __forceinline__ ull shx64(ull v, int m) {
    return __shfl_xor_sync(0xFFFFFFFFu, v, m);
}
__device__ __forceinline__ float tanh_hw(float x) {
    float r; asm("tanh.approx.f32 %0, %1;" : "=f"(r) : "f"(x)); return r;
}
__device__ __forceinline__ float sig_hw(float g) {   // g pre-scaled by 0.5
    return fmaf(0.5f, tanh_hw(g), 0.5f);
}

__global__ void __launch_bounds__(NTHR, 1) lstm_ae_kernel(
    const float* __restrict__ x,
    const float* __restrict__ ew_ih, const float* __restrict__ ew_hh,
    const float* __restrict__ eb_ih, const float* __restrict__ eb_hh,
    const float* __restrict__ dw_ih, const float* __restrict__ dw_hh,
    const float* __restrict__ db_ih, const float* __restrict__ db_hh,
    float* __restrict__ out)
{
    __shared__ __align__(16) float sm[SMEMN];
    const int tid = threadIdx.x;
    const int b0  = blockIdx.x * ROWS;

    const int pg   = tid >> 3;            // unit-pair 0..47 (warp = 4 pairs)
    const bool dec = (pg >= 32);
    const int pp   = dec ? (pg - 32) : pg;
    const int s    = tid & 7;             // k-eighth lane
    const int uu   = (s >> 2) & 1;        // my ew unit within the pair
    const int row  = s & 3;               // my elementwise row
    const int kb   = 12 * s;
    const int uA   = 2 * pp;
    const int U    = uA + uu;

    // ---- weights -> registers, gate-pair packed, activation scales folded ----
    ull w0[12], w1[12], w2[12], w3[12];
    {
        const int NU = dec ? FDIM : HDIM;
        const int KI = dec ? HDIM : FDIM;
        const int KH = dec ? FDIM : HDIM;
        const float* wih = dec ? dw_ih : ew_ih;
        const float* whh = dec ? dw_hh : ew_hh;
        #define WV(G, K) ((K) < KI ? wih[(G) * KI + (K)] : whh[(G) * KH + ((K) - KI)])
        #pragma unroll
        for (int j = 0; j < 12; ++j) {
            const int k = kb + j;
            w0[j] = pk(0.5f * WV(uA, k),          0.5f * WV(uA + NU, k));        // (I,F) A
            w1[j] = pk(WV(uA + 2 * NU, k),        0.5f * WV(uA + 3 * NU, k));    // (G,O) A
            w2[j] = pk(0.5f * WV(uA + 1, k),      0.5f * WV(uA + 1 + NU, k));    // (I,F) B
            w3[j] = pk(WV(uA + 1 + 2 * NU, k),    0.5f * WV(uA + 1 + 3 * NU, k)); // (G,O) B
        }
        #undef WV
    }

    // ---- packed pre-scaled biases, carried only on lane s==0 ----
    ull bIFa = 0ull, bGOa = 0ull, bIFb = 0ull, bGOb = 0ull;
    {
        const int NU = dec ? FDIM : HDIM;
        const float* bih = dec ? db_ih : eb_ih;
        const float* bhh = dec ? db_hh : eb_hh;
        if (s == 0) {
            #define BV(G) (bih[G] + bhh[G])
            bIFa = pk(0.5f * BV(uA),            0.5f * BV(uA + NU));
            bGOa = pk(BV(uA + 2 * NU),          0.5f * BV(uA + 3 * NU));
            bIFb = pk(0.5f * BV(uA + 1),        0.5f * BV(uA + 1 + NU));
            bGOb = pk(BV(uA + 1 + 2 * NU),      0.5f * BV(uA + 1 + 3 * NU));
            #undef BV
        }
    }

    // ---- init state; x(0); prefetch x(1). dec lanes cover 4x32 x-slots ----
    for (int i = tid; i < SMEMN; i += NTHR) sm[i] = 0.0f;
    __syncthreads();
    const float* xp = x + ((size_t)(b0 + row) * T_STEPS) * FDIM + U;  // dec only
    float* outp = out + ((size_t)(b0 + row) * T_STEPS) * FDIM + U;    // dec only
    float x_pref = 0.0f;
    if (dec) {
        sm[OFF_XHE(0) + row * XHP + U] = xp[0];
        x_pref = xp[FDIM];
        xp += 2 * FDIM;   // points at x(2)
    }
    __syncthreads();

    // row offsets in permuted slot order (s^l)&3
    const int ro0 = ((s)     & 3) * XHP;
    const int ro1 = ((s ^ 1) & 3) * XHP;
    const int ro2 = ((s ^ 2) & 3) * XHP;
    const int ro3 = ((s ^ 3) & 3) * XHP;

    float c_st = 0.0f;

    // ===== one full step: FMA + reduce + elementwise =====
    #define KS(J, F)                                                     \
    {                                                                    \
        ull hd = pk(F, F);                                               \
        c0 = ffma2(w0[J], hd, c0);                                       \
        c1 = ffma2(w1[J], hd, c1);                                       \
        c2 = ffma2(w2[J], hd, c2);                                       \
        c3 = ffma2(w3[J], hd, c3);                                       \
    }
    #define DO_ROW(XH, RO, O0, O1, O2, O3)                               \
    {                                                                    \
        const float4* hp = reinterpret_cast<const float4*>((XH) + (RO)); \
        float4 v0 = hp[0], v1 = hp[1], v2 = hp[2];                       \
        ull c0 = bIFa, c1 = bGOa, c2 = bIFb, c3 = bGOb;                  \
        KS(0, v0.x) KS(1, v0.y) KS(2, v0.z) KS(3, v0.w)                  \
        KS(4, v1.x) KS(5, v1.y) KS(6, v1.z) KS(7, v1.w)                  \
        KS(8, v2.x) KS(9, v2.y) KS(10, v2.z) KS(11, v2.w)                \
        O0 = c0; O1 = c1; O2 = c2; O3 = c3;                              \
    }
    // ENC_LIVE/DEC_LIVE are compile-time in each expansion
    #define STEP(IT, ENC_LIVE, DEC_LIVE)                                     \
    {                                                                        \
        const int rb = (IT) & 1, wb = rb ^ 1;                                \
        const float* xh = sm + (dec ? OFF_XHD(rb) : OFF_XHE(rb)) + kb;       \
        ull p0, p1, p2, p3, q0, q1, q2, q3;                                  \
        ull t0, t1, t2, t3;                                                  \
        DO_ROW(xh, ro0, p0, p1, p2, p3)                                      \
        DO_ROW(xh, ro1, q0, q1, q2, q3)                                      \
        t0 = padd2(p0, shx64(q0, 1));                                        \
        t1 = padd2(p1, shx64(q1, 1));                                        \
        t2 = padd2(p2, shx64(q2, 1));                                        \
        t3 = padd2(p3, shx64(q3, 1));                                        \
        DO_ROW(xh, ro2, p0, p1, p2, p3)                                      \
        DO_ROW(xh, ro3, q0, q1, q2, q3)                                      \
        p0 = padd2(p0, shx64(q0, 1));                                        \
        p1 = padd2(p1, shx64(q1, 1));                                        \
        p2 = padd2(p2, shx64(q2, 1));                                        \
        p3 = padd2(p3, shx64(q3, 1));                                        \
        t0 = padd2(t0, shx64(p0, 2));                                        \
        t1 = padd2(t1, shx64(p1, 2));                                        \
        t2 = padd2(t2, shx64(p2, 2));                                        \
        t3 = padd2(t3, shx64(p3, 2));                                        \
        ull keepIF = uu ? t2 : t0;                                           \
        ull keepGO = uu ? t3 : t1;                                           \
        ull sendIF = uu ? t0 : t2;                                           \
        ull sendGO = uu ? t1 : t3;                                           \
        ull cIF = padd2(keepIF, shx64(sendIF, 4));                           \
        ull cGO = padd2(keepGO, shx64(sendGO, 4));                           \
        U64F2 uf; float gi, gf, gg, go;                                      \
        uf.u = cIF; gi = uf.f.x; gf = uf.f.y;                                \
        uf.u = cGO; gg = uf.f.x; go = uf.f.y;                                \
        if (!dec) {                                                          \
            if (ENC_LIVE) {                                                  \
                float iv = sig_hw(gi), fv = sig_hw(gf);                      \
                float gv = tanh_hw(gg), ov = sig_hw(go);                     \
                c_st = fv * c_st + iv * gv;                                  \
                float hv = ov * tanh_hw(c_st);                               \
                sm[OFF_XHE(wb) + row * XHP + FDIM + U] = hv;                 \
                sm[OFF_XHD(wb) + row * XHP + U]        = hv;                 \
            }                                                                \
        } else {                                                             \
            if (DEC_LIVE) {                                                  \
                float iv = sig_hw(gi), fv = sig_hw(gf);                      \
                float gv = tanh_hw(gg), ov = sig_hw(go);                     \
                c_st = fv * c_st + iv * gv;                                  \
                float hv = ov * tanh_hw(c_st);                               \
                sm[OFF_XHD(wb) + row * XHP + HDIM + U] = hv;                 \
                *outp = hv;                                                  \
                outp += FDIM;                                                \
            }                                                                \
            if ((IT) + 1 < T_STEPS)                                          \
                sm[OFF_XHE(wb) + row * XHP + U] = x_pref;                    \
            if ((IT) + 2 < T_STEPS) {                                        \
                x_pref = *xp;                                                \
                xp += FDIM;                                                  \
            }                                                                \
        }                                                                    \
        __syncthreads();                                                     \
    }

    // peeled first step: encoder only
    STEP(0, true, false)
    // steady body: both live, no predicates on the ew paths
    for (int it = 1; it < T_STEPS; ++it) {
        STEP(it, true, true)
    }
    // peeled last step: decoder only
    STEP(T_STEPS, false, true)

    #undef STEP
    #undef DO_ROW
    #undef KS
}

extern "C" void kernel_launch(void* const* d_in, const int* in_sizes, int n_in,
                              void* d_out, int out_size)
{
    (void)in_sizes; (void)n_in; (void)out_size;
    lstm_ae_kernel<<<NBLK, NTHR>>>(
        (const float*)d_in[0],
        (const float*)d_in[1], (const float*)d_in[2],
        (const float*)d_in[3], (const float*)d_in[4],
        (const float*)d_in[5], (const float*)d_in[6],
        (const float*)d_in[7], (const float*)d_in[8],
        (float*)d_out);
}

// round 14
// speedup vs baseline: 1.9175x; 1.0095x over previous
#include <cuda_runtime.h>

// LSTM autoencoder: enc (F=32 -> H=64), dec (H=64 -> F=32), B=512, T=1024.
// 128 blocks x 384 threads, 4 batch rows/block.
// tid = pg*8 + s: pg = unit-PAIR (0..31 enc, 32..47 dec), s = k-eighth lane.
// Thread owns 8 gates (2 units x i,f,g,o) over k-eighth [12s,12s+12),
// weights packed gate-pairwise in 4 ull chains x 12 (ffma2 does 2 gates/op).
// CHAIN-ROLE SWAP: chains c0/c1 always hold MY unit's (IF)/(GO), c2/c3 the
// partner unit's -> the xor4 stage is a select-free symmetric exchange:
//   cIF = t0 + shx(t2,4), cGO = t1 + shx(t3,4).
// IF chains reduced first so the i/f MUFU tanh issues while GO shfls fly.
// ALL activations on the HW tanh MUFU (5 x tanh.approx per ew):
//   i,f,o chains pre-scaled 0.5 -> sig = fma(0.5, tanh_hw(g), 0.5)
//   g chains 1.0 -> tanh_hw(g);  tanh(c) = tanh_hw(c)
// Biases folded into lane-0 accumulator init (slot l = row l's unique
// contribution; lane 0 has uu=0 so bias arrangement matches its chains).
// XHP=104: bank base 8*((s^l)&3)+12s distinct mod 32 -> conflict-free LDS.128
// (and 4-way broadcast across the warp's 4 pair-groups).
// Double-buffered xh, ONE __syncthreads/step, decoder lags encoder 1 step,
// first/last steps peeled so the steady body is predicate-free.

#define T_STEPS 1024
#define FDIM    32
#define HDIM    64
#define ROWS    4
#define NBLK    128
#define NTHR    384
#define XHP     104

#define OFF_XHE(b) ((b) * (ROWS * XHP))
#define OFF_XHD(b) (2 * ROWS * XHP + (b) * (ROWS * XHP))
#define SMEMN      (4 * ROWS * XHP)

typedef unsigned long long ull;
union U64F2 { ull u; float2 f; };

__device__ __forceinline__ ull pk(float lo, float hi) {
    U64F2 u; u.f = make_float2(lo, hi); return u.u;
}
__device__ __forceinline__ ull ffma2(ull a, ull b, ull c) {
    ull d;
    asm("fma.rn.f32x2 %0, %1, %2, %3;" : "=l"(d) : "l"(a), "l"(b), "l"(c));
    return d;
}
__device__ __forceinline__ ull padd2(ull a, ull b) {
    ull d;
    asm("add.rn.f32x2 %0, %1, %2;" : "=l"(d) : "l"(a), "l"(b));
    return d;
}
__device__ __forceinline__ ull shx64(ull v, int m) {
    return __shfl_xor_sync(0xFFFFFFFFu, v, m);
}
__device__ __forceinline__ float tanh_hw(float x) {
    float r; asm("tanh.approx.f32 %0, %1;" : "=f"(r) : "f"(x)); return r;
}
__device__ __forceinline__ float sig_hw(float g) {   // g pre-scaled by 0.5
    return fmaf(0.5f, tanh_hw(g), 0.5f);
}

__global__ void __launch_bounds__(NTHR, 1) lstm_ae_kernel(
    const float* __restrict__ x,
    const float* __restrict__ ew_ih, const float* __restrict__ ew_hh,
    const float* __restrict__ eb_ih, const float* __restrict__ eb_hh,
    const float* __restrict__ dw_ih, const float* __restrict__ dw_hh,
    const float* __restrict__ db_ih, const float* __restrict__ db_hh,
    float* __restrict__ out)
{
    __shared__ __align__(16) float sm[SMEMN];
    const int tid = threadIdx.x;
    const int b0  = blockIdx.x * ROWS;

    const int pg   = tid >> 3;            // unit-pair 0..47 (warp = 4 pairs)
    const bool dec = (pg >= 32);
    const int pp   = dec ? (pg - 32) : pg;
    const int s    = tid & 7;             // k-eighth lane
    const int uu   = (s >> 2) & 1;        // my ew unit within the pair
    const int row  = s & 3;               // my elementwise row
    const int kb   = 12 * s;
    const int uA   = 2 * pp;
    const int U    = uA + uu;             // my unit -> chains c0/c1
    const int Uo   = uA + (uu ^ 1);       // partner unit -> chains c2/c3

    // ---- weights -> registers: c0/c1 = MY unit (IF)/(GO), c2/c3 = partner ----
    ull w0[12], w1[12], w2[12], w3[12];
    {
        const int NU = dec ? FDIM : HDIM;
        const int KI = dec ? HDIM : FDIM;
        const int KH = dec ? FDIM : HDIM;
        const float* wih = dec ? dw_ih : ew_ih;
        const float* whh = dec ? dw_hh : ew_hh;
        #define WV(G, K) ((K) < KI ? wih[(G) * KI + (K)] : whh[(G) * KH + ((K) - KI)])
        #pragma unroll
        for (int j = 0; j < 12; ++j) {
            const int k = kb + j;
            w0[j] = pk(0.5f * WV(U, k),        0.5f * WV(U + NU, k));      // my (I,F)
            w1[j] = pk(WV(U + 2 * NU, k),      0.5f * WV(U + 3 * NU, k));  // my (G,O)
            w2[j] = pk(0.5f * WV(Uo, k),       0.5f * WV(Uo + NU, k));     // ot (I,F)
            w3[j] = pk(WV(Uo + 2 * NU, k),     0.5f * WV(Uo + 3 * NU, k)); // ot (G,O)
        }
        #undef WV
    }

    // ---- packed pre-scaled biases, carried only on lane s==0 (uu=0) ----
    ull bIFa = 0ull, bGOa = 0ull, bIFb = 0ull, bGOb = 0ull;
    {
        const int NU = dec ? FDIM : HDIM;
        const float* bih = dec ? db_ih : eb_ih;
        const float* bhh = dec ? db_hh : eb_hh;
        if (s == 0) {   // lane 0: U = uA, Uo = uA+1
            #define BV(G) (bih[G] + bhh[G])
            bIFa = pk(0.5f * BV(uA),            0.5f * BV(uA + NU));
            bGOa = pk(BV(uA + 2 * NU),          0.5f * BV(uA + 3 * NU));
            bIFb = pk(0.5f * BV(uA + 1),        0.5f * BV(uA + 1 + NU));
            bGOb = pk(BV(uA + 1 + 2 * NU),      0.5f * BV(uA + 1 + 3 * NU));
            #undef BV
        }
    }

    // ---- init state; x(0); prefetch x(1). dec lanes cover 4x32 x-slots ----
    for (int i = tid; i < SMEMN; i += NTHR) sm[i] = 0.0f;
    __syncthreads();
    const float* xp = x + ((size_t)(b0 + row) * T_STEPS) * FDIM + U;  // dec only
    float* outp = out + ((size_t)(b0 + row) * T_STEPS) * FDIM + U;    // dec only
    float x_pref = 0.0f;
    if (dec) {
        sm[OFF_XHE(0) + row * XHP + U] = xp[0];
        x_pref = xp[FDIM];
        xp += 2 * FDIM;   // points at x(2)
    }
    __syncthreads();

    // row offsets in permuted slot order (s^l)&3
    const int ro0 = ((s)     & 3) * XHP;
    const int ro1 = ((s ^ 1) & 3) * XHP;
    const int ro2 = ((s ^ 2) & 3) * XHP;
    const int ro3 = ((s ^ 3) & 3) * XHP;

    float c_st = 0.0f;

    #define KS(J, F)                                                     \
    {                                                                    \
        ull hd = pk(F, F);                                               \
        c0 = ffma2(w0[J], hd, c0);                                       \
        c1 = ffma2(w1[J], hd, c1);                                       \
        c2 = ffma2(w2[J], hd, c2);                                       \
        c3 = ffma2(w3[J], hd, c3);                                       \
    }
    #define DO_ROW(XH, RO, O0, O1, O2, O3)                               \
    {                                                                    \
        const float4* hp = reinterpret_cast<const float4*>((XH) + (RO)); \
        float4 v0 = hp[0], v1 = hp[1], v2 = hp[2];                       \
        ull c0 = bIFa, c1 = bGOa, c2 = bIFb, c3 = bGOb;                  \
        KS(0, v0.x) KS(1, v0.y) KS(2, v0.z) KS(3, v0.w)                  \
        KS(4, v1.x) KS(5, v1.y) KS(6, v1.z) KS(7, v1.w)                  \
        KS(8, v2.x) KS(9, v2.y) KS(10, v2.z) KS(11, v2.w)                \
        O0 = c0; O1 = c1; O2 = c2; O3 = c3;                              \
    }
    #define STEP(IT, ENC_LIVE, DEC_LIVE)                                     \
    {                                                                        \
        const int rb = (IT) & 1, wb = rb ^ 1;                                \
        const float* xh = sm + (dec ? OFF_XHD(rb) : OFF_XHE(rb)) + kb;       \
        ull p0, p1, p2, p3, q0, q1, q2, q3;                                  \
        ull t0, t1, t2, t3;                                                  \
        DO_ROW(xh, ro0, p0, p1, p2, p3)                                      \
        DO_ROW(xh, ro1, q0, q1, q2, q3)                                      \
        t0 = padd2(p0, shx64(q0, 1));                                        \
        t1 = padd2(p1, shx64(q1, 1));                                        \
        t2 = padd2(p2, shx64(q2, 1));                                        \
        t3 = padd2(p3, shx64(q3, 1));                                        \
        DO_ROW(xh, ro2, p0, p1, p2, p3)                                      \
        DO_ROW(xh, ro3, q0, q1, q2, q3)                                      \
        p0 = padd2(p0, shx64(q0, 1));                                        \
        p2 = padd2(p2, shx64(q2, 1));                                        \
        /* IF chains first: xor2 then select-free xor4 exchange */           \
        t0 = padd2(t0, shx64(p0, 2));                                        \
        t2 = padd2(t2, shx64(p2, 2));                                        \
        ull cIF = padd2(t0, shx64(t2, 4));                                   \
        U64F2 uf; float gi, gf, gg, go;                                      \
        uf.u = cIF; gi = uf.f.x; gf = uf.f.y;                                \
        float iv = sig_hw(gi), fv = sig_hw(gf);  /* MUFU overlaps GO shfl */ \
        p1 = padd2(p1, shx64(q1, 1));                                        \
        p3 = padd2(p3, shx64(q3, 1));                                        \
        t1 = padd2(t1, shx64(p1, 2));                                        \
        t3 = padd2(t3, shx64(p3, 2));                                        \
        ull cGO = padd2(t1, shx64(t3, 4));                                   \
        uf.u = cGO; gg = uf.f.x; go = uf.f.y;                                \
        if (!dec) {                                                          \
            if (ENC_LIVE) {                                                  \
                float gv = tanh_hw(gg), ov = sig_hw(go);                     \
                c_st = fv * c_st + iv * gv;                                  \
                float hv = ov * tanh_hw(c_st);                               \
                sm[OFF_XHE(wb) + row * XHP + FDIM + U] = hv;                 \
                sm[OFF_XHD(wb) + row * XHP + U]        = hv;                 \
            }                                                                \
        } else {                                                             \
            if (DEC_LIVE) {                                                  \
                float gv = tanh_hw(gg), ov = sig_hw(go);                     \
                c_st = fv * c_st + iv * gv;                                  \
                float hv = ov * tanh_hw(c_st);                               \
                sm[OFF_XHD(wb) + row * XHP + HDIM + U] = hv;                 \
                *outp = hv;                                                  \
                outp += FDIM;                                                \
            }                                                                \
            if ((IT) + 1 < T_STEPS)                                          \
                sm[OFF_XHE(wb) + row * XHP + U] = x_pref;                    \
            if ((IT) + 2 < T_STEPS) {                                        \
                x_pref = *xp;                                                \
                xp += FDIM;                                                  \
            }                                                                \
        }                                                                    \
        __syncthreads();                                                     \
    }

    // peeled first step: encoder only
    STEP(0, true, false)
    // steady body: both live, predicate-free ew paths
    for (int it = 1; it < T_STEPS; ++it) {
        STEP(it, true, true)
    }
    // peeled last step: decoder only
    STEP(T_STEPS, false, true)

    #undef STEP
    #undef DO_ROW
    #undef KS
}

extern "C" void kernel_launch(void* const* d_in, const int* in_sizes, int n_in,
                              void* d_out, int out_size)
{
    (void)in_sizes; (void)n_in; (void)out_size;
    lstm_ae_kernel<<<NBLK, NTHR>>>(
        (const float*)d_in[0],
        (const float*)d_in[1], (const float*)d_in[2],
        (const float*)d_in[3], (const float*)d_in[4],
        (const float*)d_in[5], (const float*)d_in[6],
        (const float*)d_in[7], (const float*)d_in[8],
        (float*)d_out);
}